// round 6
// baseline (speedup 1.0000x reference)
#include <cuda_runtime.h>
#include <cuda_bf16.h>
#include <cuda_fp16.h>
#include <math.h>
#include <stdint.h>

// Problem constants
#define BATCH   4
#define TSEQ    2048
#define DMODEL  1024
#define NHEADS  16
#define DHEAD   64
#define MTOK    (BATCH * TSEQ)       // 8192 rows
#define QKV_N   (3 * DMODEL)         // 3072

// Scratch (no cudaMalloc allowed). Q/K split bf16 + V fp16 in [b,h,t,d].
__device__ __nv_bfloat16 g_Qh[(size_t)MTOK * DMODEL];
__device__ __nv_bfloat16 g_Ql[(size_t)MTOK * DMODEL];
__device__ __nv_bfloat16 g_Kh[(size_t)MTOK * DMODEL];
__device__ __nv_bfloat16 g_Kl[(size_t)MTOK * DMODEL];
__device__ __half        g_Vh[(size_t)MTOK * DMODEL];
// Pre-split GEMM operands
__device__ __nv_bfloat16 g_xh[(size_t)MTOK * DMODEL];
__device__ __nv_bfloat16 g_xl[(size_t)MTOK * DMODEL];
__device__ __nv_bfloat16 g_wqh[(size_t)DMODEL * QKV_N];
__device__ __nv_bfloat16 g_wql[(size_t)DMODEL * QKV_N];
__device__ __nv_bfloat16 g_woh[(size_t)DMODEL * DMODEL];
__device__ __nv_bfloat16 g_wol[(size_t)DMODEL * DMODEL];
__device__ __nv_bfloat16 g_ah[(size_t)MTOK * DMODEL];   // attention out hi/lo
__device__ __nv_bfloat16 g_al[(size_t)MTOK * DMODEL];

// ---------------------------------------------------------------------------
// PTX helpers
// ---------------------------------------------------------------------------
__device__ __forceinline__ uint32_t smem_u32(const void* p) {
    uint32_t a;
    asm("{ .reg .u64 t; cvta.to.shared.u64 t, %1; cvt.u32.u64 %0, t; }"
        : "=r"(a) : "l"(p));
    return a;
}
__device__ __forceinline__ void ldmx4(uint32_t* r, uint32_t addr) {
    asm volatile("ldmatrix.sync.aligned.m8n8.x4.shared.b16 {%0,%1,%2,%3}, [%4];"
                 : "=r"(r[0]), "=r"(r[1]), "=r"(r[2]), "=r"(r[3]) : "r"(addr));
}
__device__ __forceinline__ void ldmx4t(uint32_t* r, uint32_t addr) {
    asm volatile("ldmatrix.sync.aligned.m8n8.x4.trans.shared.b16 {%0,%1,%2,%3}, [%4];"
                 : "=r"(r[0]), "=r"(r[1]), "=r"(r[2]), "=r"(r[3]) : "r"(addr));
}
__device__ __forceinline__ void mma_bf(float* c, const uint32_t* a, const uint32_t* b) {
    asm volatile(
        "mma.sync.aligned.m16n8k16.row.col.f32.bf16.bf16.f32 "
        "{%0,%1,%2,%3}, {%4,%5,%6,%7}, {%8,%9}, {%0,%1,%2,%3};"
        : "+f"(c[0]), "+f"(c[1]), "+f"(c[2]), "+f"(c[3])
        : "r"(a[0]), "r"(a[1]), "r"(a[2]), "r"(a[3]), "r"(b[0]), "r"(b[1]));
}
__device__ __forceinline__ void mma_hf(float* c, const uint32_t* a, const uint32_t* b) {
    asm volatile(
        "mma.sync.aligned.m16n8k16.row.col.f32.f16.f16.f32 "
        "{%0,%1,%2,%3}, {%4,%5,%6,%7}, {%8,%9}, {%0,%1,%2,%3};"
        : "+f"(c[0]), "+f"(c[1]), "+f"(c[2]), "+f"(c[3])
        : "r"(a[0]), "r"(a[1]), "r"(a[2]), "r"(a[3]), "r"(b[0]), "r"(b[1]));
}
__device__ __forceinline__ uint32_t ex2_f16x2(uint32_t x) {
    uint32_t r;
    asm("ex2.approx.f16x2 %0, %1;" : "=r"(r) : "r"(x));
    return r;
}
__device__ __forceinline__ void cpa16(uint32_t dst, const void* src) {
    asm volatile("cp.async.cg.shared.global [%0], [%1], 16;" :: "r"(dst), "l"(src));
}
// SW128 swizzle for 128-byte-pitch rows
__device__ __forceinline__ uint32_t sw128(int row, int byteoff) {
    return (uint32_t)(row * 128 + (byteoff ^ ((row & 7) << 4)));
}
__device__ __forceinline__ void bfsplit2(float a, float b, uint32_t& hi, uint32_t& lo) {
    __nv_bfloat162 h, l;
    h.x = __float2bfloat16_rn(a);
    h.y = __float2bfloat16_rn(b);
    l.x = __float2bfloat16_rn(a - __bfloat162float(h.x));
    l.y = __float2bfloat16_rn(b - __bfloat162float(h.y));
    hi = *(uint32_t*)&h;
    lo = *(uint32_t*)&l;
}

// ---------------------------------------------------------------------------
// fp32 -> bf16 hi/lo split (memory-bound)
// ---------------------------------------------------------------------------
__global__ __launch_bounds__(256) void split_bf16(
    const float* __restrict__ in, __nv_bfloat16* __restrict__ hi,
    __nv_bfloat16* __restrict__ lo, int n4)
{
    int i = blockIdx.x * blockDim.x + threadIdx.x;
    if (i >= n4) return;
    float4 v = ((const float4*)in)[i];
    uint32_t h0, l0, h1, l1;
    bfsplit2(v.x, v.y, h0, l0);
    bfsplit2(v.z, v.w, h1, l1);
    ((uint2*)hi)[i] = make_uint2(h0, h1);
    ((uint2*)lo)[i] = make_uint2(l0, l1);
}

// ---------------------------------------------------------------------------
// Tensor-core GEMM, bf16 hi/lo 3-term. CTA 128x128, BK=32, 256 threads,
// cp.async double buffer. A smem: 128B rows = hi(64B)|lo(64B), SW128 swizzle.
// MODE 0: qkv epilogue — scatter-split into g_Qh/Ql/Kh/Kl/Vh [b,h,t,d].
// MODE 1: plain fp32 C.
// ---------------------------------------------------------------------------
#define GPAD_B 136
#define G_OFF_BH 16384
#define G_OFF_BL (G_OFF_BH + 32 * GPAD_B * 2)      // 25088
#define G_STAGE  (G_OFF_BL + 32 * GPAD_B * 2)      // 33792
#define GEMM_SMEM (2 * G_STAGE)                    // 67584

template<int MODE>
__global__ __launch_bounds__(256, 2) void tc_gemm2(
    const __nv_bfloat16* __restrict__ Ah, const __nv_bfloat16* __restrict__ Al,
    const __nv_bfloat16* __restrict__ Bh, const __nv_bfloat16* __restrict__ Bl,
    float* __restrict__ C, int M, int N, int K)
{
    extern __shared__ char sm[];
    const uint32_t smb = smem_u32(sm);

    const int tid  = threadIdx.x;
    const int lane = tid & 31;
    const int wid  = tid >> 5;
    const int wm   = wid & 1;
    const int wn   = wid >> 1;
    const int crow = blockIdx.y * 128;
    const int ccol = blockIdx.x * 128;

    // cp.async coords
    const int arow = tid >> 1;                 // A row 0..127
    const int ac0  = (tid & 1) * 2;            // A 16B-chunk pair (of 4 hi chunks)
    const int brow0 = tid >> 4;                // B rows tid>>4, +16
    const int bch   = (tid & 15) * 8;          // B elem chunk

    auto prefetch = [&](int c) {
        const uint32_t sb = smb + (uint32_t)(c & 1) * G_STAGE;
        const int ka = c * 32;
        const __nv_bfloat16* gh = Ah + (size_t)(crow + arow) * K + ka + ac0 * 8;
        const __nv_bfloat16* gl = Al + (size_t)(crow + arow) * K + ka + ac0 * 8;
        #pragma unroll
        for (int q = 0; q < 2; q++) {
            cpa16(sb + sw128(arow, (ac0 + q) * 16), gh + q * 8);
            cpa16(sb + sw128(arow, 64 + (ac0 + q) * 16), gl + q * 8);
        }
        #pragma unroll
        for (int j = 0; j < 2; j++) {
            int r = brow0 + j * 16;
            cpa16(sb + G_OFF_BH + (uint32_t)(r * GPAD_B + bch) * 2,
                  Bh + (size_t)(ka + r) * N + ccol + bch);
            cpa16(sb + G_OFF_BL + (uint32_t)(r * GPAD_B + bch) * 2,
                  Bl + (size_t)(ka + r) * N + ccol + bch);
        }
        asm volatile("cp.async.commit_group;" ::: "memory");
    };

    const int aRowBase = wm * 64 + (lane & 15);
    const int aColB    = (lane >> 4) * 16;       // bytes
    const int bKrow    = (lane & 7) + ((lane >> 3) & 1) * 8;
    const int bNBase   = wn * 32 + (lane >> 4) * 8;

    float acc[4][4][4];
    #pragma unroll
    for (int i = 0; i < 4; i++)
        #pragma unroll
        for (int j = 0; j < 4; j++)
            #pragma unroll
            for (int r = 0; r < 4; r++) acc[i][j][r] = 0.f;

    const int nchunks = K >> 5;
    prefetch(0);

    for (int c = 0; c < nchunks; c++) {
        if (c + 1 < nchunks) {
            prefetch(c + 1);
            asm volatile("cp.async.wait_group 1;" ::: "memory");
        } else {
            asm volatile("cp.async.wait_group 0;" ::: "memory");
        }
        __syncthreads();

        const uint32_t sb  = smb + (uint32_t)(c & 1) * G_STAGE;
        const uint32_t bBh = sb + G_OFF_BH;
        const uint32_t bBl = sb + G_OFF_BL;

        #pragma unroll
        for (int ks = 0; ks < 2; ks++) {
            uint32_t ah[4][4], al[4][4], bh[2][4], bl[2][4];
            #pragma unroll
            for (int mf = 0; mf < 4; mf++) {
                int r = aRowBase + mf * 16;
                ldmx4(ah[mf], sb + sw128(r, ks * 32 + aColB));
                ldmx4(al[mf], sb + sw128(r, 64 + ks * 32 + aColB));
            }
            #pragma unroll
            for (int nf2 = 0; nf2 < 2; nf2++) {
                uint32_t off = (uint32_t)((ks * 16 + bKrow) * GPAD_B + bNBase + nf2 * 16) * 2;
                ldmx4t(bh[nf2], bBh + off);
                ldmx4t(bl[nf2], bBl + off);
            }
            #pragma unroll
            for (int mf = 0; mf < 4; mf++)
                #pragma unroll
                for (int nf = 0; nf < 4; nf++) {
                    const uint32_t* bhp = &bh[nf >> 1][(nf & 1) * 2];
                    const uint32_t* blp = &bl[nf >> 1][(nf & 1) * 2];
                    mma_bf(acc[mf][nf], ah[mf], bhp);
                    mma_bf(acc[mf][nf], ah[mf], blp);
                    mma_bf(acc[mf][nf], al[mf], bhp);
                }
        }
        __syncthreads();
    }

    if (MODE == 1) {
        #pragma unroll
        for (int mf = 0; mf < 4; mf++) {
            int row0 = crow + wm * 64 + mf * 16 + (lane >> 2);
            #pragma unroll
            for (int nf = 0; nf < 4; nf++) {
                int col = ccol + wn * 32 + nf * 8 + (lane & 3) * 2;
                *(float2*)&C[(size_t)row0 * N + col] =
                    make_float2(acc[mf][nf][0], acc[mf][nf][1]);
                *(float2*)&C[(size_t)(row0 + 8) * N + col] =
                    make_float2(acc[mf][nf][2], acc[mf][nf][3]);
            }
        }
    } else {
        // scatter-split qkv epilogue: n -> (sect, head, d); m -> (b, t)
        #pragma unroll
        for (int mf = 0; mf < 4; mf++) {
            int m0 = crow + wm * 64 + mf * 16 + (lane >> 2);
            #pragma unroll
            for (int nf = 0; nf < 4; nf++) {
                int n = ccol + wn * 32 + nf * 8 + (lane & 3) * 2;
                int sect = n >> 10;
                int hh   = (n >> 6) & 15;
                int d    = n & 63;
                #pragma unroll
                for (int r2 = 0; r2 < 2; r2++) {
                    int m = m0 + r2 * 8;
                    int bb = m >> 11, t = m & 2047;
                    size_t di = (((size_t)(bb * 16 + hh) * 2048) + t) * 64 + d;
                    float o0 = acc[mf][nf][r2 * 2], o1 = acc[mf][nf][r2 * 2 + 1];
                    if (sect == 2) {
                        __half2 hv = __floats2half2_rn(o0, o1);
                        *(__half2*)&g_Vh[di] = hv;
                    } else {
                        uint32_t hi, lo;
                        bfsplit2(o0, o1, hi, lo);
                        if (sect == 0) {
                            *(uint32_t*)&g_Qh[di] = hi;
                            *(uint32_t*)&g_Ql[di] = lo;
                        } else {
                            *(uint32_t*)&g_Kh[di] = hi;
                            *(uint32_t*)&g_Kl[di] = lo;
                        }
                    }
                }
            }
        }
    }
}

// ---------------------------------------------------------------------------
// Tensor-core causal flash attention on pre-split [b,h,t,d] operands.
// CTA: 128 q-rows; kv tiles of 64. Writes bf16 hi/lo output directly.
// smem: Qh 16K | Ql 16K | Kh 8K | Kl 8K | V 8K = 56 KB, SW128 128B rows.
// ---------------------------------------------------------------------------
#define ATTN_SMEM (16384 * 2 + 8192 * 3)

__global__ __launch_bounds__(256, 2) void flash_attn_tc2(
    const __nv_bfloat16* __restrict__ Qh, const __nv_bfloat16* __restrict__ Ql,
    const __nv_bfloat16* __restrict__ Kh, const __nv_bfloat16* __restrict__ Kl,
    const __half* __restrict__ Vh,
    __nv_bfloat16* __restrict__ oh, __nv_bfloat16* __restrict__ ol)
{
    extern __shared__ char smraw[];
    char* pQh = smraw;
    char* pQl = smraw + 16384;
    char* pKh = smraw + 32768;
    char* pKl = pKh + 8192;
    char* pV  = pKl + 8192;

    const int tid = threadIdx.x, lane = tid & 31, wid = tid >> 5;
    const int b  = blockIdx.y >> 4;
    const int h  = blockIdx.y & 15;
    const int qt = gridDim.x - 1 - blockIdx.x;   // heavy tiles first
    const int q0 = qt * 128;

    const size_t hbase = (size_t)(b * 16 + h) * 2048;
    const __nv_bfloat16* gQh = Qh + (hbase + q0) * 64;
    const __nv_bfloat16* gQl = Ql + (hbase + q0) * 64;

    // Load Q tiles (128 rows x 128B), swizzled
    #pragma unroll
    for (int i = 0; i < 4; i++) {
        int li = i * 256 + tid;
        int r = li >> 3, ch = li & 7;
        uint32_t so = sw128(r, ch * 16);
        *(uint4*)(pQh + so) = *(const uint4*)(gQh + r * 64 + ch * 8);
        *(uint4*)(pQl + so) = *(const uint4*)(gQl + r * 64 + ch * 8);
    }

    const uint32_t aQh = smem_u32(pQh), aQl = smem_u32(pQl);
    const uint32_t aKh = smem_u32(pKh), aKl = smem_u32(pKl);
    const uint32_t aV  = smem_u32(pV);

    const int rowQ = wid * 16 + (lane & 15);
    const int colB = (lane >> 4) * 16;              // bytes
    const int kRow = lane & 15;
    const int vRow = (lane & 7) + ((lane >> 3) & 1) * 8;

    float accO[8][4];
    #pragma unroll
    for (int i = 0; i < 8; i++)
        #pragma unroll
        for (int r = 0; r < 4; r++) accO[i][r] = 0.f;
    float lr = 0.f, lr8 = 0.f;

    const int rowbase = q0 + wid * 16;
    const int nkt = 2 * qt + 2;
    const float csc = 0.1803368802f;   // log2(e)/8

    for (int kt = 0; kt < nkt; kt++) {
        const int kv0 = kt * 64;
        __syncthreads();

        const __nv_bfloat16* gKh = Kh + (hbase + kv0) * 64;
        const __nv_bfloat16* gKl = Kl + (hbase + kv0) * 64;
        const __half*        gV  = Vh + (hbase + kv0) * 64;
        #pragma unroll
        for (int i = 0; i < 2; i++) {
            int li = i * 256 + tid;
            int r = li >> 3, ch = li & 7;
            uint32_t so = sw128(r, ch * 16);
            *(uint4*)(pKh + so) = *(const uint4*)(gKh + r * 64 + ch * 8);
            *(uint4*)(pKl + so) = *(const uint4*)(gKl + r * 64 + ch * 8);
            *(uint4*)(pV  + so) = *(const uint4*)(gV  + r * 64 + ch * 8);
        }
        __syncthreads();

        // --- S = Q K^T ---
        float S[8][4];
        #pragma unroll
        for (int i = 0; i < 8; i++)
            #pragma unroll
            for (int r = 0; r < 4; r++) S[i][r] = 0.f;

        #pragma unroll
        for (int ks = 0; ks < 4; ks++) {
            uint32_t ah[4], al[4];
            ldmx4(ah, aQh + sw128(rowQ, ks * 32 + colB));
            ldmx4(al, aQl + sw128(rowQ, ks * 32 + colB));
            #pragma unroll
            for (int g = 0; g < 4; g++) {
                uint32_t kh[4], kl[4];
                int r = g * 16 + kRow;
                ldmx4(kh, aKh + sw128(r, ks * 32 + colB));
                ldmx4(kl, aKl + sw128(r, ks * 32 + colB));
                uint32_t be[2]  = {kh[0], kh[2]};
                uint32_t bo[2]  = {kh[1], kh[3]};
                uint32_t bel[2] = {kl[0], kl[2]};
                uint32_t bol[2] = {kl[1], kl[3]};
                mma_bf(S[2*g],   ah, be);
                mma_bf(S[2*g],   ah, bel);
                mma_bf(S[2*g],   al, be);
                mma_bf(S[2*g+1], ah, bo);
                mma_bf(S[2*g+1], ah, bol);
                mma_bf(S[2*g+1], al, bo);
            }
        }

        // --- causal mask ---
        if (kv0 + 63 > rowbase) {
            int r0 = rowbase + (lane >> 2);
            #pragma unroll
            for (int nf = 0; nf < 8; nf++) {
                int c0 = kv0 + nf * 8 + (lane & 3) * 2;
                if (c0 > r0)          S[nf][0] = -1e5f;
                if (c0 + 1 > r0)      S[nf][1] = -1e5f;
                if (c0 > r0 + 8)      S[nf][2] = -1e5f;
                if (c0 + 1 > r0 + 8)  S[nf][3] = -1e5f;
            }
        }

        // --- P = exp(S) (fp16 A-frag layout) + row sums ---
        uint32_t P[8][2];
        #pragma unroll
        for (int nf = 0; nf < 8; nf++) {
            __half2 h0 = __floats2half2_rn(S[nf][0] * csc, S[nf][1] * csc);
            __half2 h1 = __floats2half2_rn(S[nf][2] * csc, S[nf][3] * csc);
            uint32_t p0 = ex2_f16x2(*(uint32_t*)&h0);
            uint32_t p1 = ex2_f16x2(*(uint32_t*)&h1);
            P[nf][0] = p0;
            P[nf][1] = p1;
            float2 f0 = __half22float2(*(__half2*)&p0);
            float2 f1 = __half22float2(*(__half2*)&p1);
            lr  += f0.x + f0.y;
            lr8 += f1.x + f1.y;
        }

        // --- O += P @ V ---
        #pragma unroll
        for (int j = 0; j < 4; j++) {
            uint32_t a[4] = { P[2*j][0], P[2*j][1], P[2*j+1][0], P[2*j+1][1] };
            int r = j * 16 + vRow;
            #pragma unroll
            for (int dg = 0; dg < 2; dg++) {
                uint32_t vv[4], vv2[4];
                ldmx4t(vv,  aV + sw128(r, dg * 64 + colB));
                ldmx4t(vv2, aV + sw128(r, dg * 64 + 32 + colB));
                mma_hf(accO[4*dg + 0], a, &vv[0]);
                mma_hf(accO[4*dg + 1], a, &vv[2]);
                mma_hf(accO[4*dg + 2], a, &vv2[0]);
                mma_hf(accO[4*dg + 3], a, &vv2[2]);
            }
        }
    }

    lr  += __shfl_xor_sync(0xffffffffu, lr, 1);
    lr  += __shfl_xor_sync(0xffffffffu, lr, 2);
    lr8 += __shfl_xor_sync(0xffffffffu, lr8, 1);
    lr8 += __shfl_xor_sync(0xffffffffu, lr8, 2);
    const float inv  = 1.f / lr;
    const float inv8 = 1.f / lr8;

    const int grow = b * TSEQ + q0 + wid * 16 + (lane >> 2);
    #pragma unroll
    for (int dg = 0; dg < 8; dg++) {
        int col = h * DHEAD + dg * 8 + (lane & 3) * 2;
        uint32_t hi, lo;
        bfsplit2(accO[dg][0] * inv, accO[dg][1] * inv, hi, lo);
        size_t i0 = (size_t)grow * DMODEL + col;
        *(uint32_t*)&oh[i0] = hi;
        *(uint32_t*)&ol[i0] = lo;
        bfsplit2(accO[dg][2] * inv8, accO[dg][3] * inv8, hi, lo);
        size_t i1 = (size_t)(grow + 8) * DMODEL + col;
        *(uint32_t*)&oh[i1] = hi;
        *(uint32_t*)&ol[i1] = lo;
    }
}

// ---------------------------------------------------------------------------
extern "C" void kernel_launch(void* const* d_in, const int* in_sizes, int n_in,
                              void* d_out, int out_size)
{
    const float* x     = (const float*)d_in[0];
    const float* W_qkv = (const float*)d_in[1];
    const float* W_out = (const float*)d_in[2];
    float* out = (float*)d_out;

    __nv_bfloat16 *xh, *xl, *wqh, *wql, *woh, *wol, *ah, *al;
    __nv_bfloat16 *Qh, *Ql, *Kh, *Kl;
    __half *Vh;
    cudaGetSymbolAddress((void**)&xh,  g_xh);
    cudaGetSymbolAddress((void**)&xl,  g_xl);
    cudaGetSymbolAddress((void**)&wqh, g_wqh);
    cudaGetSymbolAddress((void**)&wql, g_wql);
    cudaGetSymbolAddress((void**)&woh, g_woh);
    cudaGetSymbolAddress((void**)&wol, g_wol);
    cudaGetSymbolAddress((void**)&ah,  g_ah);
    cudaGetSymbolAddress((void**)&al,  g_al);
    cudaGetSymbolAddress((void**)&Qh,  g_Qh);
    cudaGetSymbolAddress((void**)&Ql,  g_Ql);
    cudaGetSymbolAddress((void**)&Kh,  g_Kh);
    cudaGetSymbolAddress((void**)&Kl,  g_Kl);
    cudaGetSymbolAddress((void**)&Vh,  g_Vh);

    cudaFuncSetAttribute(tc_gemm2<0>, cudaFuncAttributeMaxDynamicSharedMemorySize,
                         GEMM_SMEM);
    cudaFuncSetAttribute(tc_gemm2<1>, cudaFuncAttributeMaxDynamicSharedMemorySize,
                         GEMM_SMEM);
    cudaFuncSetAttribute(flash_attn_tc2, cudaFuncAttributeMaxDynamicSharedMemorySize,
                         ATTN_SMEM);

    // 0) Split inputs
    {
        int n4 = MTOK * DMODEL / 4;
        split_bf16<<<(n4 + 255) / 256, 256>>>(x, xh, xl, n4);
        int w4 = DMODEL * QKV_N / 4;
        split_bf16<<<(w4 + 255) / 256, 256>>>(W_qkv, wqh, wql, w4);
        int o4 = DMODEL * DMODEL / 4;
        split_bf16<<<(o4 + 255) / 256, 256>>>(W_out, woh, wol, o4);
    }

    // 1) QKV projection -> pre-split Q/K (bf16 hi/lo) + V (fp16), [b,h,t,d]
    tc_gemm2<0><<<dim3(QKV_N / 128, MTOK / 128), 256, GEMM_SMEM>>>(
        xh, xl, wqh, wql, nullptr, MTOK, QKV_N, DMODEL);

    // 2) Causal flash attention -> bf16 hi/lo output
    flash_attn_tc2<<<dim3(TSEQ / 128, BATCH * NHEADS), 256, ATTN_SMEM>>>(
        Qh, Ql, Kh, Kl, Vh, ah, al);

    // 3) Output projection (fp32 out)
    tc_gemm2<1><<<dim3(DMODEL / 128, MTOK / 128), 256, GEMM_SMEM>>>(
        ah, al, woh, wol, out, MTOK, DMODEL, DMODEL);
}

// round 7
// speedup vs baseline: 1.0407x; 1.0407x over previous
#include <cuda_runtime.h>
#include <cuda_bf16.h>
#include <cuda_fp16.h>
#include <math.h>
#include <stdint.h>

// Problem constants
#define BATCH   4
#define TSEQ    2048
#define DMODEL  1024
#define NHEADS  16
#define DHEAD   64
#define MTOK    (BATCH * TSEQ)       // 8192 rows
#define QKV_N   (3 * DMODEL)         // 3072

// Scratch (no cudaMalloc). All per-token layouts are [tok][1024] (h*64+d).
__device__ __nv_bfloat16 g_Qh[(size_t)MTOK * DMODEL];
__device__ __nv_bfloat16 g_Ql[(size_t)MTOK * DMODEL];
__device__ __nv_bfloat16 g_Kh[(size_t)MTOK * DMODEL];
__device__ __nv_bfloat16 g_Kl[(size_t)MTOK * DMODEL];
__device__ __half        g_Vh[(size_t)MTOK * DMODEL];
__device__ __nv_bfloat16 g_xh[(size_t)MTOK * DMODEL];
__device__ __nv_bfloat16 g_xl[(size_t)MTOK * DMODEL];
__device__ __nv_bfloat16 g_wqh[(size_t)DMODEL * QKV_N];
__device__ __nv_bfloat16 g_wql[(size_t)DMODEL * QKV_N];
__device__ __nv_bfloat16 g_woh[(size_t)DMODEL * DMODEL];
__device__ __nv_bfloat16 g_wol[(size_t)DMODEL * DMODEL];
__device__ __nv_bfloat16 g_ah[(size_t)MTOK * DMODEL];   // attention out hi/lo
__device__ __nv_bfloat16 g_al[(size_t)MTOK * DMODEL];

// ---------------------------------------------------------------------------
// PTX helpers
// ---------------------------------------------------------------------------
__device__ __forceinline__ uint32_t smem_u32(const void* p) {
    uint32_t a;
    asm("{ .reg .u64 t; cvta.to.shared.u64 t, %1; cvt.u32.u64 %0, t; }"
        : "=r"(a) : "l"(p));
    return a;
}
__device__ __forceinline__ void ldmx4(uint32_t* r, uint32_t addr) {
    asm volatile("ldmatrix.sync.aligned.m8n8.x4.shared.b16 {%0,%1,%2,%3}, [%4];"
                 : "=r"(r[0]), "=r"(r[1]), "=r"(r[2]), "=r"(r[3]) : "r"(addr));
}
__device__ __forceinline__ void ldmx4t(uint32_t* r, uint32_t addr) {
    asm volatile("ldmatrix.sync.aligned.m8n8.x4.trans.shared.b16 {%0,%1,%2,%3}, [%4];"
                 : "=r"(r[0]), "=r"(r[1]), "=r"(r[2]), "=r"(r[3]) : "r"(addr));
}
__device__ __forceinline__ void mma_bf(float* c, const uint32_t* a, const uint32_t* b) {
    asm volatile(
        "mma.sync.aligned.m16n8k16.row.col.f32.bf16.bf16.f32 "
        "{%0,%1,%2,%3}, {%4,%5,%6,%7}, {%8,%9}, {%0,%1,%2,%3};"
        : "+f"(c[0]), "+f"(c[1]), "+f"(c[2]), "+f"(c[3])
        : "r"(a[0]), "r"(a[1]), "r"(a[2]), "r"(a[3]), "r"(b[0]), "r"(b[1]));
}
__device__ __forceinline__ void mma_hf(float* c, const uint32_t* a, const uint32_t* b) {
    asm volatile(
        "mma.sync.aligned.m16n8k16.row.col.f32.f16.f16.f32 "
        "{%0,%1,%2,%3}, {%4,%5,%6,%7}, {%8,%9}, {%0,%1,%2,%3};"
        : "+f"(c[0]), "+f"(c[1]), "+f"(c[2]), "+f"(c[3])
        : "r"(a[0]), "r"(a[1]), "r"(a[2]), "r"(a[3]), "r"(b[0]), "r"(b[1]));
}
__device__ __forceinline__ uint32_t ex2_f16x2(uint32_t x) {
    uint32_t r;
    asm("ex2.approx.f16x2 %0, %1;" : "=r"(r) : "r"(x));
    return r;
}
__device__ __forceinline__ void cpa16(uint32_t dst, const void* src) {
    asm volatile("cp.async.cg.shared.global [%0], [%1], 16;" :: "r"(dst), "l"(src));
}
// SW128 swizzle for 128-byte-pitch rows (attention smem only)
__device__ __forceinline__ uint32_t sw128(int row, int byteoff) {
    return (uint32_t)(row * 128 + (byteoff ^ ((row & 7) << 4)));
}
__device__ __forceinline__ void bfsplit2(float a, float b, uint32_t& hi, uint32_t& lo) {
    __nv_bfloat162 h, l;
    h.x = __float2bfloat16_rn(a);
    h.y = __float2bfloat16_rn(b);
    l.x = __float2bfloat16_rn(a - __bfloat162float(h.x));
    l.y = __float2bfloat16_rn(b - __bfloat162float(h.y));
    hi = *(uint32_t*)&h;
    lo = *(uint32_t*)&l;
}

// ---------------------------------------------------------------------------
// fp32 -> bf16 hi/lo split
// ---------------------------------------------------------------------------
__global__ __launch_bounds__(256) void split_bf16(
    const float* __restrict__ in, __nv_bfloat16* __restrict__ hi,
    __nv_bfloat16* __restrict__ lo, int n4)
{
    int i = blockIdx.x * blockDim.x + threadIdx.x;
    if (i >= n4) return;
    float4 v = ((const float4*)in)[i];
    uint32_t h0, l0, h1, l1;
    bfsplit2(v.x, v.y, h0, l0);
    bfsplit2(v.z, v.w, h1, l1);
    ((uint2*)hi)[i] = make_uint2(h0, h1);
    ((uint2*)lo)[i] = make_uint2(l0, l1);
}

// ---------------------------------------------------------------------------
// Tensor-core GEMM, bf16 hi/lo 3-term — R5 core (PAD layout, linear addr).
// MODE 0: qkv epilogue -> split into g_Qh/Ql/Kh/Kl/Vh ([tok][1024] each).
// MODE 1: plain fp32 C.
// ---------------------------------------------------------------------------
#define GPAD_A 40
#define GPAD_B 136
#define STAGE_A (128 * GPAD_A)
#define STAGE_B (32 * GPAD_B)
#define STAGE_ELEMS (2 * STAGE_A + 2 * STAGE_B)
#define GEMM_SMEM (2 * STAGE_ELEMS * 2)

template<int MODE>
__global__ __launch_bounds__(256, 2) void tc_gemm3(
    const __nv_bfloat16* __restrict__ Ah, const __nv_bfloat16* __restrict__ Al,
    const __nv_bfloat16* __restrict__ Bh, const __nv_bfloat16* __restrict__ Bl,
    float* __restrict__ C, int M, int N, int K)
{
    extern __shared__ __nv_bfloat16 sm[];
    const uint32_t smb = smem_u32(sm);

    const int tid  = threadIdx.x;
    const int lane = tid & 31;
    const int wid  = tid >> 5;
    const int wm   = wid & 1;
    const int wn   = wid >> 1;
    const int crow = blockIdx.y * 128;
    const int ccol = blockIdx.x * 128;

    const int arow0 = tid >> 2;
    const int ach   = (tid & 3) * 8;
    const int brow0 = tid >> 4;
    const int bch   = (tid & 15) * 8;

    auto prefetch = [&](int c) {
        const uint32_t sb = smb + (uint32_t)(c & 1) * (STAGE_ELEMS * 2);
        const size_t ka = (size_t)c * 32;
        #pragma unroll
        for (int j = 0; j < 2; j++) {
            int row = arow0 + j * 64;
            const __nv_bfloat16* sh = Ah + (size_t)(crow + row) * K + ka + ach;
            const __nv_bfloat16* sl = Al + (size_t)(crow + row) * K + ka + ach;
            uint32_t d = sb + (uint32_t)(row * GPAD_A + ach) * 2;
            cpa16(d, sh);
            cpa16(d + STAGE_A * 2, sl);
        }
        #pragma unroll
        for (int j = 0; j < 2; j++) {
            int row = brow0 + j * 16;
            const __nv_bfloat16* sh = Bh + (ka + row) * N + ccol + bch;
            const __nv_bfloat16* sl = Bl + (ka + row) * N + ccol + bch;
            uint32_t d = sb + (uint32_t)(2 * STAGE_A + row * GPAD_B + bch) * 2;
            cpa16(d, sh);
            cpa16(d + STAGE_B * 2, sl);
        }
        asm volatile("cp.async.commit_group;" ::: "memory");
    };

    const int aRowBase = wm * 64 + (lane & 15);
    const int aColOff  = (lane >> 4) * 8;
    const int bKrow    = (lane & 7) + ((lane >> 3) & 1) * 8;
    const int bNBase   = wn * 32 + (lane >> 4) * 8;

    float acc[4][4][4];
    #pragma unroll
    for (int i = 0; i < 4; i++)
        #pragma unroll
        for (int j = 0; j < 4; j++)
            #pragma unroll
            for (int r = 0; r < 4; r++) acc[i][j][r] = 0.f;

    const int nchunks = K >> 5;
    prefetch(0);

    for (int c = 0; c < nchunks; c++) {
        if (c + 1 < nchunks) {
            prefetch(c + 1);
            asm volatile("cp.async.wait_group 1;" ::: "memory");
        } else {
            asm volatile("cp.async.wait_group 0;" ::: "memory");
        }
        __syncthreads();

        const uint32_t sb  = smb + (uint32_t)(c & 1) * (STAGE_ELEMS * 2);
        const uint32_t bAh = sb;
        const uint32_t bAl = sb + STAGE_A * 2;
        const uint32_t bBh = sb + 2 * STAGE_A * 2;
        const uint32_t bBl = bBh + STAGE_B * 2;

        #pragma unroll
        for (int ks = 0; ks < 2; ks++) {
            uint32_t ah[4][4], al[4][4], bh[2][4], bl[2][4];
            #pragma unroll
            for (int mf = 0; mf < 4; mf++) {
                uint32_t off = (uint32_t)((aRowBase + mf * 16) * GPAD_A + ks * 16 + aColOff) * 2;
                ldmx4(ah[mf], bAh + off);
                ldmx4(al[mf], bAl + off);
            }
            #pragma unroll
            for (int nf2 = 0; nf2 < 2; nf2++) {
                uint32_t off = (uint32_t)((ks * 16 + bKrow) * GPAD_B + bNBase + nf2 * 16) * 2;
                ldmx4t(bh[nf2], bBh + off);
                ldmx4t(bl[nf2], bBl + off);
            }
            #pragma unroll
            for (int mf = 0; mf < 4; mf++)
                #pragma unroll
                for (int nf = 0; nf < 4; nf++) {
                    const uint32_t* bhp = &bh[nf >> 1][(nf & 1) * 2];
                    const uint32_t* blp = &bl[nf >> 1][(nf & 1) * 2];
                    mma_bf(acc[mf][nf], ah[mf], bhp);
                    mma_bf(acc[mf][nf], ah[mf], blp);
                    mma_bf(acc[mf][nf], al[mf], bhp);
                }
        }
        __syncthreads();
    }

    if (MODE == 1) {
        #pragma unroll
        for (int mf = 0; mf < 4; mf++) {
            int row0 = crow + wm * 64 + mf * 16 + (lane >> 2);
            #pragma unroll
            for (int nf = 0; nf < 4; nf++) {
                int col = ccol + wn * 32 + nf * 8 + (lane & 3) * 2;
                *(float2*)&C[(size_t)row0 * N + col] =
                    make_float2(acc[mf][nf][0], acc[mf][nf][1]);
                *(float2*)&C[(size_t)(row0 + 8) * N + col] =
                    make_float2(acc[mf][nf][2], acc[mf][nf][3]);
            }
        }
    } else {
        // qkv split epilogue. n -> sect (q/k/v) + col (h*64+d), [tok][1024].
        const int nbase = ccol + wn * 32;
        const int sect  = nbase >> 10;          // whole 128-wide tile in one sect
        #pragma unroll
        for (int mf = 0; mf < 4; mf++) {
            int m0 = crow + wm * 64 + mf * 16 + (lane >> 2);
            #pragma unroll
            for (int nf = 0; nf < 4; nf++) {
                int col = (nbase + nf * 8 + (lane & 3) * 2) & 1023;
                #pragma unroll
                for (int r2 = 0; r2 < 2; r2++) {
                    size_t di = (size_t)(m0 + r2 * 8) * 1024 + col;
                    float o0 = acc[mf][nf][r2 * 2], o1 = acc[mf][nf][r2 * 2 + 1];
                    if (sect == 2) {
                        __half2 hv = __floats2half2_rn(o0, o1);
                        *(__half2*)&g_Vh[di] = hv;
                    } else {
                        uint32_t hi, lo;
                        bfsplit2(o0, o1, hi, lo);
                        if (sect == 0) {
                            *(uint32_t*)&g_Qh[di] = hi;
                            *(uint32_t*)&g_Ql[di] = lo;
                        } else {
                            *(uint32_t*)&g_Kh[di] = hi;
                            *(uint32_t*)&g_Kl[di] = lo;
                        }
                    }
                }
            }
        }
    }
}

// ---------------------------------------------------------------------------
// Tensor-core causal flash attention (R6 kernel, [tok][1024] operands).
// smem: Qh 16K | Ql 16K | Kh 8K | Kl 8K | V 8K = 56 KB, SW128 128B rows.
// ---------------------------------------------------------------------------
#define ATTN_SMEM (16384 * 2 + 8192 * 3)

__global__ __launch_bounds__(256, 2) void flash_attn_tc3(
    const __nv_bfloat16* __restrict__ Qh, const __nv_bfloat16* __restrict__ Ql,
    const __nv_bfloat16* __restrict__ Kh, const __nv_bfloat16* __restrict__ Kl,
    const __half* __restrict__ Vh,
    __nv_bfloat16* __restrict__ oh, __nv_bfloat16* __restrict__ ol)
{
    extern __shared__ char smraw[];
    char* pQh = smraw;
    char* pQl = smraw + 16384;
    char* pKh = smraw + 32768;
    char* pKl = pKh + 8192;
    char* pV  = pKl + 8192;

    const int tid = threadIdx.x, lane = tid & 31, wid = tid >> 5;
    const int b  = blockIdx.y >> 4;
    const int h  = blockIdx.y & 15;
    const int qt = gridDim.x - 1 - blockIdx.x;   // heavy tiles first
    const int q0 = qt * 128;

    // [tok][1024] layout: row = b*2048 + t, col = h*64 + d
    const size_t rbase = (size_t)b * 2048;
    const int    cbase = h * 64;

    // Load Q tiles (128 rows x 128B), swizzled
    #pragma unroll
    for (int i = 0; i < 4; i++) {
        int li = i * 256 + tid;
        int r = li >> 3, ch = li & 7;
        size_t gi = (rbase + q0 + r) * 1024 + cbase + ch * 8;
        uint32_t so = sw128(r, ch * 16);
        *(uint4*)(pQh + so) = *(const uint4*)(Qh + gi);
        *(uint4*)(pQl + so) = *(const uint4*)(Ql + gi);
    }

    const uint32_t aQh = smem_u32(pQh), aQl = smem_u32(pQl);
    const uint32_t aKh = smem_u32(pKh), aKl = smem_u32(pKl);
    const uint32_t aV  = smem_u32(pV);

    const int rowQ = wid * 16 + (lane & 15);
    const int colB = (lane >> 4) * 16;              // bytes
    const int kRow = lane & 15;
    const int vRow = (lane & 7) + ((lane >> 3) & 1) * 8;

    float accO[8][4];
    #pragma unroll
    for (int i = 0; i < 8; i++)
        #pragma unroll
        for (int r = 0; r < 4; r++) accO[i][r] = 0.f;
    float lr = 0.f, lr8 = 0.f;

    const int rowbase = q0 + wid * 16;
    const int nkt = 2 * qt + 2;
    const float csc = 0.1803368802f;   // log2(e)/8

    for (int kt = 0; kt < nkt; kt++) {
        const int kv0 = kt * 64;
        __syncthreads();

        #pragma unroll
        for (int i = 0; i < 2; i++) {
            int li = i * 256 + tid;
            int r = li >> 3, ch = li & 7;
            size_t gi = (rbase + kv0 + r) * 1024 + cbase + ch * 8;
            uint32_t so = sw128(r, ch * 16);
            *(uint4*)(pKh + so) = *(const uint4*)(Kh + gi);
            *(uint4*)(pKl + so) = *(const uint4*)(Kl + gi);
            *(uint4*)(pV  + so) = *(const uint4*)(Vh + gi);
        }
        __syncthreads();

        // --- S = Q K^T ---
        float S[8][4];
        #pragma unroll
        for (int i = 0; i < 8; i++)
            #pragma unroll
            for (int r = 0; r < 4; r++) S[i][r] = 0.f;

        #pragma unroll
        for (int ks = 0; ks < 4; ks++) {
            uint32_t ah[4], al[4];
            ldmx4(ah, aQh + sw128(rowQ, ks * 32 + colB));
            ldmx4(al, aQl + sw128(rowQ, ks * 32 + colB));
            #pragma unroll
            for (int g = 0; g < 4; g++) {
                uint32_t kh[4], kl[4];
                int r = g * 16 + kRow;
                ldmx4(kh, aKh + sw128(r, ks * 32 + colB));
                ldmx4(kl, aKl + sw128(r, ks * 32 + colB));
                uint32_t be[2]  = {kh[0], kh[2]};
                uint32_t bo[2]  = {kh[1], kh[3]};
                uint32_t bel[2] = {kl[0], kl[2]};
                uint32_t bol[2] = {kl[1], kl[3]};
                mma_bf(S[2*g],   ah, be);
                mma_bf(S[2*g],   ah, bel);
                mma_bf(S[2*g],   al, be);
                mma_bf(S[2*g+1], ah, bo);
                mma_bf(S[2*g+1], ah, bol);
                mma_bf(S[2*g+1], al, bo);
            }
        }

        // --- causal mask ---
        if (kv0 + 63 > rowbase) {
            int r0 = rowbase + (lane >> 2);
            #pragma unroll
            for (int nf = 0; nf < 8; nf++) {
                int c0 = kv0 + nf * 8 + (lane & 3) * 2;
                if (c0 > r0)          S[nf][0] = -1e5f;
                if (c0 + 1 > r0)      S[nf][1] = -1e5f;
                if (c0 > r0 + 8)      S[nf][2] = -1e5f;
                if (c0 + 1 > r0 + 8)  S[nf][3] = -1e5f;
            }
        }

        // --- P = exp(S) (fp16 A-frag layout) + row sums ---
        uint32_t P[8][2];
        #pragma unroll
        for (int nf = 0; nf < 8; nf++) {
            __half2 h0 = __floats2half2_rn(S[nf][0] * csc, S[nf][1] * csc);
            __half2 h1 = __floats2half2_rn(S[nf][2] * csc, S[nf][3] * csc);
            uint32_t p0 = ex2_f16x2(*(uint32_t*)&h0);
            uint32_t p1 = ex2_f16x2(*(uint32_t*)&h1);
            P[nf][0] = p0;
            P[nf][1] = p1;
            float2 f0 = __half22float2(*(__half2*)&p0);
            float2 f1 = __half22float2(*(__half2*)&p1);
            lr  += f0.x + f0.y;
            lr8 += f1.x + f1.y;
        }

        // --- O += P @ V ---
        #pragma unroll
        for (int j = 0; j < 4; j++) {
            uint32_t a[4] = { P[2*j][0], P[2*j][1], P[2*j+1][0], P[2*j+1][1] };
            int r = j * 16 + vRow;
            #pragma unroll
            for (int dg = 0; dg < 2; dg++) {
                uint32_t vv[4], vv2[4];
                ldmx4t(vv,  aV + sw128(r, dg * 64 + colB));
                ldmx4t(vv2, aV + sw128(r, dg * 64 + 32 + colB));
                mma_hf(accO[4*dg + 0], a, &vv[0]);
                mma_hf(accO[4*dg + 1], a, &vv[2]);
                mma_hf(accO[4*dg + 2], a, &vv2[0]);
                mma_hf(accO[4*dg + 3], a, &vv2[2]);
            }
        }
    }

    lr  += __shfl_xor_sync(0xffffffffu, lr, 1);
    lr  += __shfl_xor_sync(0xffffffffu, lr, 2);
    lr8 += __shfl_xor_sync(0xffffffffu, lr8, 1);
    lr8 += __shfl_xor_sync(0xffffffffu, lr8, 2);
    const float inv  = 1.f / lr;
    const float inv8 = 1.f / lr8;

    const int grow = b * TSEQ + q0 + wid * 16 + (lane >> 2);
    #pragma unroll
    for (int dg = 0; dg < 8; dg++) {
        int col = cbase + dg * 8 + (lane & 3) * 2;
        uint32_t hi, lo;
        bfsplit2(accO[dg][0] * inv, accO[dg][1] * inv, hi, lo);
        size_t i0 = (size_t)grow * DMODEL + col;
        *(uint32_t*)&oh[i0] = hi;
        *(uint32_t*)&ol[i0] = lo;
        bfsplit2(accO[dg][2] * inv8, accO[dg][3] * inv8, hi, lo);
        size_t i1 = (size_t)(grow + 8) * DMODEL + col;
        *(uint32_t*)&oh[i1] = hi;
        *(uint32_t*)&ol[i1] = lo;
    }
}

// ---------------------------------------------------------------------------
extern "C" void kernel_launch(void* const* d_in, const int* in_sizes, int n_in,
                              void* d_out, int out_size)
{
    const float* x     = (const float*)d_in[0];
    const float* W_qkv = (const float*)d_in[1];
    const float* W_out = (const float*)d_in[2];
    float* out = (float*)d_out;

    __nv_bfloat16 *xh, *xl, *wqh, *wql, *woh, *wol, *ah, *al;
    __nv_bfloat16 *Qh, *Ql, *Kh, *Kl;
    __half *Vh;
    cudaGetSymbolAddress((void**)&xh,  g_xh);
    cudaGetSymbolAddress((void**)&xl,  g_xl);
    cudaGetSymbolAddress((void**)&wqh, g_wqh);
    cudaGetSymbolAddress((void**)&wql, g_wql);
    cudaGetSymbolAddress((void**)&woh, g_woh);
    cudaGetSymbolAddress((void**)&wol, g_wol);
    cudaGetSymbolAddress((void**)&ah,  g_ah);
    cudaGetSymbolAddress((void**)&al,  g_al);
    cudaGetSymbolAddress((void**)&Qh,  g_Qh);
    cudaGetSymbolAddress((void**)&Ql,  g_Ql);
    cudaGetSymbolAddress((void**)&Kh,  g_Kh);
    cudaGetSymbolAddress((void**)&Kl,  g_Kl);
    cudaGetSymbolAddress((void**)&Vh,  g_Vh);

    cudaFuncSetAttribute(tc_gemm3<0>, cudaFuncAttributeMaxDynamicSharedMemorySize,
                         GEMM_SMEM);
    cudaFuncSetAttribute(tc_gemm3<1>, cudaFuncAttributeMaxDynamicSharedMemorySize,
                         GEMM_SMEM);
    cudaFuncSetAttribute(flash_attn_tc3, cudaFuncAttributeMaxDynamicSharedMemorySize,
                         ATTN_SMEM);

    // 0) Split inputs
    {
        int n4 = MTOK * DMODEL / 4;
        split_bf16<<<(n4 + 255) / 256, 256>>>(x, xh, xl, n4);
        int w4 = DMODEL * QKV_N / 4;
        split_bf16<<<(w4 + 255) / 256, 256>>>(W_qkv, wqh, wql, w4);
        int o4 = DMODEL * DMODEL / 4;
        split_bf16<<<(o4 + 255) / 256, 256>>>(W_out, woh, wol, o4);
    }

    // 1) QKV projection -> split Q/K (bf16 hi/lo) + V (fp16), [tok][1024]
    tc_gemm3<0><<<dim3(QKV_N / 128, MTOK / 128), 256, GEMM_SMEM>>>(
        xh, xl, wqh, wql, nullptr, MTOK, QKV_N, DMODEL);

    // 2) Causal flash attention -> bf16 hi/lo output
    flash_attn_tc3<<<dim3(TSEQ / 128, BATCH * NHEADS), 256, ATTN_SMEM>>>(
        Qh, Ql, Kh, Kl, Vh, ah, al);

    // 3) Output projection (fp32 out)
    tc_gemm3<1><<<dim3(DMODEL / 128, MTOK / 128), 256, GEMM_SMEM>>>(
        ah, al, woh, wol, out, MTOK, DMODEL, DMODEL);
}